// round 14
// baseline (speedup 1.0000x reference)
#include <cuda_runtime.h>
#include <cuda_bf16.h>

// RNN: h_t = tanh(h_{t-1} + x_t @ W1 + b1), out = sigmoid(h_63 @ W2 + b2)
// x: [B, 64, 16] f32, W1: [16,10], b1: [10], W2: [10,5], b2: [5], out: [B,5] f32
//
// Round 14: 512B DRAM bursts. Producer fetches 8-step groups: per group each
// row's 512B is loaded as 2 lanes x 256B contiguous (16 cp16/lane), one commit
// group. Ring = 2 groups = 16 step-slots (20KB/warp -> WPB=2, 40KB static,
// 5 blocks/SM). Consumer (K-pair FFMA2 per step) is byte-identical to R11.

#define SEQ   64
#define INF   16
#define HID   10
#define OUTF  5
#define ROWF  (SEQ*INF)     // 1024 floats per batch
#define RST   20            // smem row stride in floats (16B aligned)
#define BPW   16            // batches per warp
#define WPB   2             // warps per block
#define SLOT  (BPW*RST)     // 320 floats per step slot
#define GSTEP 8             // steps per fetch group
#define NGRP  (SEQ/GSTEP)   // 8 groups
#define RSTEP 16            // ring capacity in steps (2 groups)

typedef unsigned long long u64;

__device__ __forceinline__ u64 pack2(float lo, float hi) {
    u64 r; asm("mov.b64 %0, {%1,%2};" : "=l"(r) : "f"(lo), "f"(hi)); return r;
}
__device__ __forceinline__ void unpack2(float& lo, float& hi, u64 v) {
    asm("mov.b64 {%0,%1}, %2;" : "=f"(lo), "=f"(hi) : "l"(v));
}
__device__ __forceinline__ u64 fma2(u64 a, u64 b, u64 c) {
    u64 d; asm("fma.rn.f32x2 %0, %1, %2, %3;" : "=l"(d) : "l"(a), "l"(b), "l"(c)); return d;
}
__device__ __forceinline__ float tanh_fast(float x) {
    float y; asm("tanh.approx.f32 %0, %1;" : "=f"(y) : "f"(x)); return y;
}
__device__ __forceinline__ float sigmoid_fast(float x) {
    float e; asm("ex2.approx.f32 %0, %1;" : "=f"(e) : "f"(x * -1.4426950408889634f));
    float r; asm("rcp.approx.f32 %0, %1;" : "=f"(r) : "f"(e + 1.0f));
    return r;
}

#define CP16(dst, src) \
    asm volatile("cp.async.cg.shared.global.L2::256B [%0], [%1], 16;" \
                 :: "r"(dst), "l"(src))
#define CPCOMMIT() asm volatile("cp.async.commit_group;")
#define CPWAIT(n)  asm volatile("cp.async.wait_group %0;" :: "n"(n))

__global__ void __launch_bounds__(WPB * 32, 5)
rnn_kernel(const float* __restrict__ x,
           const float* __restrict__ W1,
           const float* __restrict__ b1,
           const float* __restrict__ W2,
           const float* __restrict__ b2,
           float* __restrict__ out,
           int nbatch)
{
    __shared__ float buf[WPB][RSTEP * SLOT];   // 2 x 20 KB warp-private rings

    const int lane = threadIdx.x & 31;
    const int wid  = threadIdx.x >> 5;
    const int wbase = (blockIdx.x * WPB + wid) * BPW;
    if (wbase >= nbatch) return;

    const int half = lane & 1;        // which 5 hidden units
    const int bl   = lane >> 1;       // batch-local 0..15
    const int ub   = half * 5;        // first unit of this half

    // ---- weights, K-pair packed: Wq[ip][j] = (W1[2ip][ub+j], W1[2ip+1][ub+j])
    u64 Wq[8][5];
#pragma unroll
    for (int ip = 0; ip < 8; ++ip)
#pragma unroll
        for (int j = 0; j < 5; ++j)
            Wq[ip][j] = pack2(__ldg(W1 + (2*ip)*HID + ub + j),
                              __ldg(W1 + (2*ip+1)*HID + ub + j));
    float b1v[5], hb[5];
#pragma unroll
    for (int j = 0; j < 5; ++j) { b1v[j] = __ldg(b1 + ub + j); hb[j] = b1v[j]; }

    // ---- producer: row r = lane>>1 (0..15), q = lane&1 selects the 256B
    // half of the row's 512B group chunk (steps 8g+4q .. 8g+4q+3).
    const int r = lane >> 1;
    const int q = lane & 1;
    const float4* src = reinterpret_cast<const float4*>(
        x + (size_t)(wbase + r) * ROWF + q * 64);   // + 32 float4s per group
    float* sbf = &buf[wid][0];
    const unsigned sb32 = (unsigned)__cvta_generic_to_shared(sbf);
    // step (8g + 4q + k') lands in slot ((g&1)*8 + 4q + k'); row r, word k&3
    const unsigned stB = sb32 + (unsigned)(((q * 4 * SLOT) + r * RST) << 2);
    const unsigned PB  = (unsigned)(GSTEP * SLOT * 4);   // odd-group byte offset

#define ISSUE(g) do {                                                        \
        const unsigned pb_ = ((g) & 1) ? PB : 0u;                            \
        const float4* gs_ = src + 32 * (g);                                  \
        _Pragma("unroll")                                                    \
        for (int k = 0; k < 16; ++k)                                         \
            CP16(stB + pb_ + (unsigned)((((k >> 2) * SLOT) + (k & 3) * 4) << 2), \
                 gs_ + k);                                                   \
        CPCOMMIT();                                                          \
    } while (0)

    ISSUE(0);
    ISSUE(1);

    const float* myrow = sbf + bl * RST;

    for (int g = 0; g < NGRP; ++g) {
        CPWAIT(1);            // group g complete (this thread's chunks)
        __syncwarp();         // all lanes past wait -> group g slots readable

        // compute 8 steps from slots (g&1)*8 .. +7
        const unsigned cb = (unsigned)((g & 1) * (GSTEP * SLOT));
#pragma unroll
        for (int k = 0; k < GSTEP; ++k) {
            const ulonglong2* rowq =
                reinterpret_cast<const ulonglong2*>(myrow + cb + k * SLOT);
            u64 a0 = 0, a1 = 0, a2 = 0, a3 = 0, a4 = 0;
            {   // inputs 0..7
                const ulonglong2 p0 = rowq[0];
                const ulonglong2 p1 = rowq[1];
                const u64 xq[4] = {p0.x, p0.y, p1.x, p1.y};
#pragma unroll
                for (int ip = 0; ip < 4; ++ip) {
                    a0 = fma2(xq[ip], Wq[ip][0], a0);
                    a1 = fma2(xq[ip], Wq[ip][1], a1);
                    a2 = fma2(xq[ip], Wq[ip][2], a2);
                    a3 = fma2(xq[ip], Wq[ip][3], a3);
                    a4 = fma2(xq[ip], Wq[ip][4], a4);
                }
            }
            {   // inputs 8..15
                const ulonglong2 p2 = rowq[2];
                const ulonglong2 p3 = rowq[3];
                const u64 xq[4] = {p2.x, p2.y, p3.x, p3.y};
#pragma unroll
                for (int ip = 0; ip < 4; ++ip) {
                    a0 = fma2(xq[ip], Wq[4 + ip][0], a0);
                    a1 = fma2(xq[ip], Wq[4 + ip][1], a1);
                    a2 = fma2(xq[ip], Wq[4 + ip][2], a2);
                    a3 = fma2(xq[ip], Wq[4 + ip][3], a3);
                    a4 = fma2(xq[ip], Wq[4 + ip][4], a4);
                }
            }
            const u64 aa[5] = {a0, a1, a2, a3, a4};
#pragma unroll
            for (int j = 0; j < 5; ++j) {
                float lo, hi; unpack2(lo, hi, aa[j]);
                hb[j] = tanh_fast(hb[j] + (lo + hi)) + b1v[j];
            }
        }

        __syncwarp();         // all lanes done READING group g slots
        if (g + 2 < NGRP) { ISSUE(g + 2); }   // refill g's slots
        else              { CPCOMMIT(); }     // keep wait-count exact
    }

    // ---- epilogue: h = hb - b1; partial h@W2 per half, combine via shfl ----
    float hv[5];
#pragma unroll
    for (int j = 0; j < 5; ++j) hv[j] = hb[j] - b1v[j];

    float po[OUTF];
#pragma unroll
    for (int o = 0; o < OUTF; ++o) {
        float a = 0.0f;
#pragma unroll
        for (int k = 0; k < 5; ++k)
            a = fmaf(hv[k], __ldg(W2 + (ub + k) * OUTF + o), a);
        po[o] = a + __shfl_xor_sync(0xffffffffu, a, 1);
    }
    if (half == 0) {
        const long b = wbase + bl;
        if (b < nbatch) {
#pragma unroll
            for (int o = 0; o < OUTF; ++o)
                out[b * OUTF + o] = sigmoid_fast(po[o] + __ldg(b2 + o));
        }
    }
}

extern "C" void kernel_launch(void* const* d_in, const int* in_sizes, int n_in,
                              void* d_out, int out_size)
{
    const float* x  = (const float*)d_in[0];
    const float* W1 = (const float*)d_in[1];
    const float* b1 = (const float*)d_in[2];
    const float* W2 = (const float*)d_in[3];
    const float* b2 = (const float*)d_in[4];
    float* out = (float*)d_out;

    int nbatch = in_sizes[0] / ROWF;                       // 65536
    int blocks = (nbatch + WPB * BPW - 1) / (WPB * BPW);   // 2048
    rnn_kernel<<<blocks, WPB * 32>>>(x, W1, b1, W2, b2, out, nbatch);
}

// round 15
// speedup vs baseline: 1.6016x; 1.6016x over previous
#include <cuda_runtime.h>
#include <cuda_bf16.h>

// RNN: h_t = tanh(h_{t-1} + x_t @ W1 + b1), out = sigmoid(h_63 @ W2 + b2)
// x: [B, 64, 16] f32, W1: [16,10], b1: [10], W2: [10,5], b2: [5], out: [B,5] f32
//
// FINAL (R11, best measured: 49.6us, rel_err 1.6e-6, HBM 5.73TB/s = 72% peak).
// Structure: warp = 16 batches x 2 unit-halves. Per thread: 5 hidden units,
// W1 K-pair packed into 40 f32x2 regs; 40 fma2 = all 80 FMA/step, x-pairs
// straight from LDS.128. tanh via MUFU.TANH. Producer: 2 cp.async(16B) per
// thread per step with .L2::256B prefetch into an 8-slot warp-private smem
// ring, LOOKA=7, one CPWAIT+__syncwarp per step (no block barriers).
// Epilogue: per-half h@W2 partials combined with one shfl_xor.

#define SEQ   64
#define INF   16
#define HID   10
#define OUTF  5
#define ROWF  (SEQ*INF)     // 1024 floats per batch
#define RST   20            // smem row stride in floats (16B aligned)
#define BPW   16            // batches per warp
#define WPB   4             // warps per block
#define SLOT  (BPW*RST)     // 320 floats per ring slot
#define NSLOT 8             // ring slots
#define LOOKA 7             // cp.async lookahead (max = NSLOT-1)

typedef unsigned long long u64;

__device__ __forceinline__ u64 pack2(float lo, float hi) {
    u64 r; asm("mov.b64 %0, {%1,%2};" : "=l"(r) : "f"(lo), "f"(hi)); return r;
}
__device__ __forceinline__ void unpack2(float& lo, float& hi, u64 v) {
    asm("mov.b64 {%0,%1}, %2;" : "=f"(lo), "=f"(hi) : "l"(v));
}
__device__ __forceinline__ u64 fma2(u64 a, u64 b, u64 c) {
    u64 d; asm("fma.rn.f32x2 %0, %1, %2, %3;" : "=l"(d) : "l"(a), "l"(b), "l"(c)); return d;
}
__device__ __forceinline__ float tanh_fast(float x) {
    float y; asm("tanh.approx.f32 %0, %1;" : "=f"(y) : "f"(x)); return y;
}
__device__ __forceinline__ float sigmoid_fast(float x) {
    float e; asm("ex2.approx.f32 %0, %1;" : "=f"(e) : "f"(x * -1.4426950408889634f));
    float r; asm("rcp.approx.f32 %0, %1;" : "=f"(r) : "f"(e + 1.0f));
    return r;
}

// 16B async copy with 256B L2 prefetch: DRAM fetches the whole 256B region
// (4 consecutive steps of this batch row); later steps hit L2.
#define CP16(dst, src) \
    asm volatile("cp.async.cg.shared.global.L2::256B [%0], [%1], 16;" \
                 :: "r"(dst), "l"(src))
#define CPCOMMIT() asm volatile("cp.async.commit_group;")
#define CPWAIT(n)  asm volatile("cp.async.wait_group %0;" :: "n"(n))

__global__ void __launch_bounds__(WPB * 32, 4)
rnn_kernel(const float* __restrict__ x,
           const float* __restrict__ W1,
           const float* __restrict__ b1,
           const float* __restrict__ W2,
           const float* __restrict__ b2,
           float* __restrict__ out,
           int nbatch)
{
    __shared__ float buf[WPB][NSLOT * SLOT];   // 4 x 10 KB warp-private rings

    const int lane = threadIdx.x & 31;
    const int wid  = threadIdx.x >> 5;
    const int wbase = (blockIdx.x * WPB + wid) * BPW;
    if (wbase >= nbatch) return;

    const int half = lane & 1;        // which 5 hidden units
    const int bl   = lane >> 1;       // batch-local 0..15
    const int ub   = half * 5;        // first unit of this half

    // ---- weights, K-pair packed: Wq[ip][j] = (W1[2ip][ub+j], W1[2ip+1][ub+j])
    u64 Wq[8][5];
#pragma unroll
    for (int ip = 0; ip < 8; ++ip)
#pragma unroll
        for (int j = 0; j < 5; ++j)
            Wq[ip][j] = pack2(__ldg(W1 + (2*ip)*HID + ub + j),
                              __ldg(W1 + (2*ip+1)*HID + ub + j));
    float b1v[5], h[5], hb[5];
#pragma unroll
    for (int j = 0; j < 5; ++j) { b1v[j] = __ldg(b1 + ub + j); h[j] = 0.0f; hb[j] = b1v[j]; }

    // ---- producer addressing: 2 x 16B chunks per thread per step ----
    const float4* src0 = reinterpret_cast<const float4*>(
        x + (size_t)(wbase + (lane >> 2)) * ROWF) + (lane & 3);
    float* sbf = &buf[wid][0];
    const unsigned sb32 = (unsigned)__cvta_generic_to_shared(sbf);
    const unsigned st0 = sb32 + ((((lane >> 2)) * RST + (lane & 3) * 4) << 2);
    const unsigned D_ST = 8 * RST * 4;          // +8 batches in smem (bytes)

    // prologue: LOOKA steps in flight, one commit group each
#pragma unroll
    for (int k = 0; k < LOOKA; ++k) {
        const unsigned so = (unsigned)(k & (NSLOT - 1)) * (SLOT * 4);
        CP16(st0 + so,        src0 + 4 * k);
        CP16(st0 + so + D_ST, src0 + 4 * k + 2 * ROWF);   // +8 batches = 2*ROWF float4s
        CPCOMMIT();
    }

    const float* myrow = sbf + bl * RST;

#pragma unroll 2
    for (int s = 0; s < SEQ; ++s) {
        CPWAIT(LOOKA - 1);    // group s complete (this thread's chunks)
        __syncwarp();         // all lanes past wait -> slot s readable,
                              // and all lanes' reads of slot s-1 are done

        // keep pipeline full: step s+LOOKA -> slot (s+LOOKA)&7 = (s-1)&7
        {
            const int f = s + LOOKA;
            if (f < SEQ) {
                const unsigned so = (unsigned)(f & (NSLOT - 1)) * (SLOT * 4);
                CP16(st0 + so,        src0 + 4 * f);
                CP16(st0 + so + D_ST, src0 + 4 * f + 2 * ROWF);
            }
            CPCOMMIT();       // empty tail group keeps wait-count exact
        }

        // compute step s: x-pairs straight from LDS.128
        const ulonglong2* rowq =
            reinterpret_cast<const ulonglong2*>(myrow + (s & (NSLOT - 1)) * SLOT);
        u64 a0 = 0, a1 = 0, a2 = 0, a3 = 0, a4 = 0;

        {   // inputs 0..7
            const ulonglong2 p0 = rowq[0];
            const ulonglong2 p1 = rowq[1];
            const u64 xq[4] = {p0.x, p0.y, p1.x, p1.y};
#pragma unroll
            for (int ip = 0; ip < 4; ++ip) {
                a0 = fma2(xq[ip], Wq[ip][0], a0);
                a1 = fma2(xq[ip], Wq[ip][1], a1);
                a2 = fma2(xq[ip], Wq[ip][2], a2);
                a3 = fma2(xq[ip], Wq[ip][3], a3);
                a4 = fma2(xq[ip], Wq[ip][4], a4);
            }
        }
        {   // inputs 8..15
            const ulonglong2 p2 = rowq[2];
            const ulonglong2 p3 = rowq[3];
            const u64 xq[4] = {p2.x, p2.y, p3.x, p3.y};
#pragma unroll
            for (int ip = 0; ip < 4; ++ip) {
                a0 = fma2(xq[ip], Wq[4 + ip][0], a0);
                a1 = fma2(xq[ip], Wq[4 + ip][1], a1);
                a2 = fma2(xq[ip], Wq[4 + ip][2], a2);
                a3 = fma2(xq[ip], Wq[4 + ip][3], a3);
                a4 = fma2(xq[ip], Wq[4 + ip][4], a4);
            }
        }

        u64 aa[5] = {a0, a1, a2, a3, a4};
#pragma unroll
        for (int j = 0; j < 5; ++j) {
            float lo, hi; unpack2(lo, hi, aa[j]);
            h[j]  = tanh_fast(hb[j] + (lo + hi));
            hb[j] = h[j] + b1v[j];
        }
    }

    // ---- epilogue: partial h@W2 per half, combine via shfl ----
    float po[OUTF];
#pragma unroll
    for (int o = 0; o < OUTF; ++o) {
        float a = 0.0f;
#pragma unroll
        for (int k = 0; k < 5; ++k)
            a = fmaf(h[k], __ldg(W2 + (ub + k) * OUTF + o), a);
        po[o] = a + __shfl_xor_sync(0xffffffffu, a, 1);
    }
    if (half == 0) {
        const long b = wbase + bl;
        if (b < nbatch) {
#pragma unroll
            for (int o = 0; o < OUTF; ++o)
                out[b * OUTF + o] = sigmoid_fast(po[o] + __ldg(b2 + o));
        }
    }
}

extern "C" void kernel_launch(void* const* d_in, const int* in_sizes, int n_in,
                              void* d_out, int out_size)
{
    const float* x  = (const float*)d_in[0];
    const float* W1 = (const float*)d_in[1];
    const float* b1 = (const float*)d_in[2];
    const float* W2 = (const float*)d_in[3];
    const float* b2 = (const float*)d_in[4];
    float* out = (float*)d_out;

    int nbatch = in_sizes[0] / ROWF;                       // 65536
    int blocks = (nbatch + WPB * BPW - 1) / (WPB * BPW);   // 1024
    rnn_kernel<<<blocks, WPB * 32>>>(x, W1, b1, W2, b2, out, nbatch);
}